// round 12
// baseline (speedup 1.0000x reference)
#include <cuda_runtime.h>
#include <math.h>

#define NN 100000
#define EE 1000000
#define EMBD 30
#define NODE_BLOCKS 391   // ceil(100000/256)

// ---------------- scratch (static device memory; no allocs) ----------------
__device__ float4 g_f4[NN];          // (f0, f1, f2, el1) per node
__device__ float  g_er1[NN];
__device__ float4 g_agg4[NN];        // per-dst (Σp·f0, Σp·f1, Σp·f2, Σp)
__device__ float  g_el2[NN];
__device__ float2 g_ed2[NN];         // (.x = er2, .y = den2)
__device__ float  g_w[NN];           // per-src Σ alpha
__device__ float  g_himg[EMBD];
__device__ float  g_s64[64];         // Σ_n w[n] * r1[n]
__device__ int    g_ctr;

// ---------------- K1: node init + per-block wa1/wr1 + himg block ----------------
__global__ void __launch_bounds__(256) k1_init(
    const float* __restrict__ feat, const float* __restrict__ al1,
    const float* __restrict__ ar1,  const float* __restrict__ W1,
    const float* __restrict__ x,    const float* __restrict__ W_lin1,
    const float* __restrict__ w_conv2, const float* __restrict__ w_conv3)
{
    __shared__ float swa[3], swr[3];
    int t = threadIdx.x;

    if (blockIdx.x == NODE_BLOCKS) {
        // dedicated block: image head (runs concurrently with node init)
        if (t < EMBD) {
            float hi = 0.f;
            const float* row = W_lin1 + t * 512;
            for (int k = 0; k < 512; k++) hi += row[k] * x[k];
            float acc = 0.f;
            for (int k = 0; k < 64; k++) {
                float s = 1.f / (1.f + __expf(-w_conv2[k] * hi));
                acc += w_conv3[k] * s;
            }
            g_himg[t] = 1.f / (1.f + __expf(-acc));
        }
        return;
    }

    if (t < 6) {
        const float* row = W1 + (t % 3) * 128;
        const float* av  = (t < 3) ? al1 : ar1;
        float a = 0.f;
        for (int j = 0; j < 64; j++) a += row[j] * av[j];
        if (t < 3) swa[t] = a; else swr[t - 3] = a;
    }
    __syncthreads();

    if (blockIdx.x == 0) {
        if (t < 64) g_s64[t] = 0.f;
        if (t == 64) g_ctr = 0;
    }

    int n = blockIdx.x * 256 + t;
    if (n >= NN) return;
    float f0 = feat[n * 3 + 0], f1 = feat[n * 3 + 1], f2 = feat[n * 3 + 2];
    float el = f0 * swa[0] + f1 * swa[1] + f2 * swa[2];
    g_f4[n]   = make_float4(f0, f1, f2, el);
    g_er1[n]  = f0 * swr[0] + f1 * swr[1] + f2 * swr[2];
    g_agg4[n] = make_float4(0.f, 0.f, 0.f, 0.f);
    g_ed2[n]  = make_float2(0.f, 0.f);
    g_w[n]    = 0.f;
}

// ---------------- E1: layer-1 edge pass — one v4 RED per edge (2 edges/thread) ----------------
__global__ void e1_edge(const int* __restrict__ src, const int* __restrict__ dst)
{
    int i = blockIdx.x * blockDim.x + threadIdx.x;
    if (i >= EE / 2) return;
    int2 s2 = ((const int2*)src)[i];
    int2 d2 = ((const int2*)dst)[i];

    float4 fa = g_f4[s2.x];
    float4 fb = g_f4[s2.y];
    float ea = g_er1[d2.x];
    float eb = g_er1[d2.y];

    float va = fa.w + ea; va = va > 0.f ? va : 0.2f * va;
    float vb = fb.w + eb; vb = vb > 0.f ? vb : 0.2f * vb;
    float pa = __expf(va);
    float pb = __expf(vb);
    asm volatile("red.global.add.v4.f32 [%0], {%1, %2, %3, %4};"
                 :: "l"(&g_agg4[d2.x]), "f"(pa * fa.x), "f"(pa * fa.y), "f"(pa * fa.z), "f"(pa)
                 : "memory");
    asm volatile("red.global.add.v4.f32 [%0], {%1, %2, %3, %4};"
                 :: "l"(&g_agg4[d2.y]), "f"(pb * fb.x), "f"(pb * fb.y), "f"(pb * fb.z), "f"(pb)
                 : "memory");
}

// ---------------- K45: per-node normalize, 3->64 expand, relu, el2/er2 ----------------
__global__ void __launch_bounds__(256) k45_nodes(
    const float* __restrict__ W1, const float* __restrict__ b1,
    const float* __restrict__ W2, const float* __restrict__ al2,
    const float* __restrict__ ar2)
{
    __shared__ float sW1[3 * 64];
    __shared__ float sb1[64], swa2[64], swr2[64];
    int t = threadIdx.x;
    for (int idx = t; idx < 3 * 64; idx += 256)
        sW1[idx] = W1[(idx >> 6) * 128 + (idx & 63)];
    if (t < 64) {
        sb1[t] = b1[t];
        float a = 0.f;
        for (int j = 0; j < EMBD; j++) a += W2[t * 60 + j] * al2[j];
        swa2[t] = a;
    } else if (t < 128) {
        int k = t - 64;
        float a = 0.f;
        for (int j = 0; j < EMBD; j++) a += W2[k * 60 + j] * ar2[j];
        swr2[k] = a;
    }
    __syncthreads();

    int n = blockIdx.x * 256 + t;
    if (n >= NN) return;

    float4 a = g_agg4[n];
    float inv = (a.w > 0.f) ? (1.f / a.w) : 0.f;
    float a0 = a.x * inv, a1 = a.y * inv, a2 = a.z * inv;

    float el = 0.f, er = 0.f;
#pragma unroll
    for (int kc = 0; kc < 64; kc += 8) {
#pragma unroll
        for (int u = 0; u < 8; u++) {
            float v = a0 * sW1[kc + u] + a1 * sW1[64 + kc + u] + a2 * sW1[128 + kc + u]
                    + sb1[kc + u];
            v = v > 0.f ? v : 0.f;
            el += v * swa2[kc + u];
            er += v * swr2[kc + u];
        }
    }
    g_el2[n] = el;
    g_ed2[n].x = er;   // .y (den2) stays zero from k1; e2a REDs into it
}

// ---------------- E2A: layer-2 denominator RED (2 edges/thread) ----------------
__global__ void e2a_edge(const int* __restrict__ src, const int* __restrict__ dst)
{
    int i = blockIdx.x * blockDim.x + threadIdx.x;
    if (i >= EE / 2) return;
    int2 s2 = ((const int2*)src)[i];
    int2 d2 = ((const int2*)dst)[i];
    float va = g_el2[s2.x] + g_ed2[d2.x].x;
    float vb = g_el2[s2.y] + g_ed2[d2.y].x;
    va = va > 0.f ? va : 0.2f * va;
    vb = vb > 0.f ? vb : 0.2f * vb;
    atomicAdd(&g_ed2[d2.x].y, __expf(va));
    atomicAdd(&g_ed2[d2.y].y, __expf(vb));
}

// ---------------- E2C: per-src alpha sum (recompute p; 2 edges/thread) ----------------
__global__ void e2c_edge(const int* __restrict__ src, const int* __restrict__ dst)
{
    int i = blockIdx.x * blockDim.x + threadIdx.x;
    if (i >= EE / 2) return;
    int2 s2 = ((const int2*)src)[i];
    int2 d2 = ((const int2*)dst)[i];
    float2 eda = g_ed2[d2.x];   // (er2, den2) in one 8B gather
    float2 edb = g_ed2[d2.y];
    float va = g_el2[s2.x] + eda.x;
    float vb = g_el2[s2.y] + edb.x;
    va = va > 0.f ? va : 0.2f * va;
    vb = vb > 0.f ? vb : 0.2f * vb;
    atomicAdd(&g_w[s2.x], __expf(va) / eda.y);
    atomicAdd(&g_w[s2.y], __expf(vb) / edb.y);
}

// ---------------- K78: S64 reduce (recompute r1) + last-block finale ----------------
__global__ void __launch_bounds__(256) k78_final(
    const float* __restrict__ W1, const float* __restrict__ b1,
    const float* __restrict__ W2, const float* __restrict__ b2,
    const float* __restrict__ vocab, const float* __restrict__ W_lin4,
    float* __restrict__ out)
{
    __shared__ float sW1[3 * 64];
    __shared__ float sb1[64];
    __shared__ float sacc[64];
    int t = threadIdx.x;
    for (int idx = t; idx < 3 * 64; idx += 256)
        sW1[idx] = W1[(idx >> 6) * 128 + (idx & 63)];
    if (t < 64) { sb1[t] = b1[t]; sacc[t] = 0.f; }
    __syncthreads();

    int lane = t & 31, wrp = t >> 5;
    int gw = blockIdx.x * 8 + wrp;
    int nw = gridDim.x * 8;
    int j = 2 * lane;
    float w10 = sW1[j],      w11 = sW1[64 + j],      w12 = sW1[128 + j],      bb0 = sb1[j];
    float w20 = sW1[j + 1],  w21 = sW1[64 + j + 1],  w22 = sW1[128 + j + 1],  bb1 = sb1[j + 1];

    float ax = 0.f, ay = 0.f;
    for (int n = gw; n < NN; n += nw) {
        float4 a = g_agg4[n];
        float wn = g_w[n];
        float inv = (a.w > 0.f) ? (1.f / a.w) : 0.f;
        float a0 = a.x * inv, a1 = a.y * inv, a2 = a.z * inv;
        float r0 = a0 * w10 + a1 * w11 + a2 * w12 + bb0;
        float r1 = a0 * w20 + a1 * w21 + a2 * w22 + bb1;
        r0 = r0 > 0.f ? r0 : 0.f;
        r1 = r1 > 0.f ? r1 : 0.f;
        ax = fmaf(wn, r0, ax);
        ay = fmaf(wn, r1, ay);
    }
    atomicAdd(&sacc[j], ax);
    atomicAdd(&sacc[j + 1], ay);
    __syncthreads();
    if (t < 64) atomicAdd(&g_s64[t], sacc[t]);

    // last-block detection
    __threadfence();
    __syncthreads();
    __shared__ int isLast;
    if (t == 0) isLast = (atomicAdd(&g_ctr, 1) == (int)gridDim.x - 1);
    __syncthreads();
    if (!isLast) return;

    __shared__ float h[70];
    __shared__ float l[2];
    if (t < 30) {
        float acc = 0.f;
        for (int k = 0; k < 64; k++) acc += __ldcg(&g_s64[k]) * W2[k * 60 + t];
        h[t] = acc * (1.f / (float)NN) + b2[t];
    }
    else if (t < 60) h[t] = g_himg[t - 30];
    else if (t < 70) h[t] = vocab[t - 60];
    __syncthreads();
    if (t < 2) {
        float acc = 0.f;
        for (int k = 0; k < 70; k++) acc += W_lin4[t * 70 + k] * h[k];
        l[t] = acc;
    }
    __syncthreads();
    if (t < 2) {
        float m = fmaxf(l[0], l[1]);
        float lse = m + logf(expf(l[0] - m) + expf(l[1] - m));
        out[t] = l[t] - lse;
    }
}

// ---------------- launch ----------------
extern "C" void kernel_launch(void* const* d_in, const int* in_sizes, int n_in,
                              void* d_out, int out_size)
{
    const float* x       = (const float*)d_in[0];
    const float* feat    = (const float*)d_in[1];
    const float* vocab   = (const float*)d_in[2];
    const int*   src     = (const int*)d_in[3];
    const int*   dst     = (const int*)d_in[4];
    const float* W_lin1  = (const float*)d_in[5];
    const float* w_conv2 = (const float*)d_in[6];
    const float* w_conv3 = (const float*)d_in[7];
    const float* W_lin4  = (const float*)d_in[8];
    const float* W1      = (const float*)d_in[9];
    const float* al1     = (const float*)d_in[10];
    const float* ar1     = (const float*)d_in[11];
    const float* b1      = (const float*)d_in[12];
    const float* W2      = (const float*)d_in[13];
    const float* al2     = (const float*)d_in[14];
    const float* ar2     = (const float*)d_in[15];
    const float* b2      = (const float*)d_in[16];
    float* out = (float*)d_out;

    k1_init<<<NODE_BLOCKS + 1, 256>>>(feat, al1, ar1, W1, x, W_lin1, w_conv2, w_conv3);
    e1_edge<<<(EE / 2 + 255) / 256, 256>>>(src, dst);
    k45_nodes<<<(NN + 255) / 256, 256>>>(W1, b1, W2, al2, ar2);
    e2a_edge<<<(EE / 2 + 255) / 256, 256>>>(src, dst);
    e2c_edge<<<(EE / 2 + 255) / 256, 256>>>(src, dst);
    k78_final<<<160, 256>>>(W1, b1, W2, b2, vocab, W_lin4, out);
}

// round 16
// speedup vs baseline: 1.0365x; 1.0365x over previous
#include <cuda_runtime.h>
#include <math.h>

#define NN 100000
#define EE 1000000
#define EMBD 30
#define NODE_BLOCKS 391   // ceil(100000/256)

// ---------------- scratch (static device memory; no allocs) ----------------
__device__ float4 g_f4[NN];          // (f0, f1, f2, el1) per node
__device__ float  g_er1[NN];
__device__ float4 g_agg4[NN];        // per-dst (Σp·f0, Σp·f1, Σp·f2, Σp)
__device__ float  g_el2[NN], g_er2[NN], g_den2[NN], g_w[NN];
__device__ float  g_p2[EE];
__device__ float  g_himg[EMBD];
__device__ float  g_s64[64];         // Σ_n w[n] * r1[n]
__device__ int    g_ctr;

// ---------------- K1: node init + per-block wa1/wr1 + himg block ----------------
__global__ void __launch_bounds__(256) k1_init(
    const float* __restrict__ feat, const float* __restrict__ al1,
    const float* __restrict__ ar1,  const float* __restrict__ W1,
    const float* __restrict__ x,    const float* __restrict__ W_lin1,
    const float* __restrict__ w_conv2, const float* __restrict__ w_conv3)
{
    __shared__ float swa[3], swr[3];
    int t = threadIdx.x;

    if (blockIdx.x == NODE_BLOCKS) {
        // dedicated block: image head (runs concurrently with node init)
        if (t < EMBD) {
            float hi = 0.f;
            const float* row = W_lin1 + t * 512;
            for (int k = 0; k < 512; k++) hi += row[k] * x[k];
            float acc = 0.f;
            for (int k = 0; k < 64; k++) {
                float s = 1.f / (1.f + __expf(-w_conv2[k] * hi));
                acc += w_conv3[k] * s;
            }
            g_himg[t] = 1.f / (1.f + __expf(-acc));
        }
        return;
    }

    if (t < 6) {
        const float* row = W1 + (t % 3) * 128;
        const float* av  = (t < 3) ? al1 : ar1;
        float a = 0.f;
        for (int j = 0; j < 64; j++) a += row[j] * av[j];
        if (t < 3) swa[t] = a; else swr[t - 3] = a;
    }
    __syncthreads();

    if (blockIdx.x == 0) {
        if (t < 64) g_s64[t] = 0.f;
        if (t == 64) g_ctr = 0;
    }

    int n = blockIdx.x * 256 + t;
    if (n >= NN) return;
    float f0 = feat[n * 3 + 0], f1 = feat[n * 3 + 1], f2 = feat[n * 3 + 2];
    float el = f0 * swa[0] + f1 * swa[1] + f2 * swa[2];
    g_f4[n]   = make_float4(f0, f1, f2, el);
    g_er1[n]  = f0 * swr[0] + f1 * swr[1] + f2 * swr[2];
    g_agg4[n] = make_float4(0.f, 0.f, 0.f, 0.f);
    g_den2[n] = 0.f;
    g_w[n]    = 0.f;
}

// ---------------- E1: layer-1 edge pass — one v4 RED per edge ----------------
__global__ void e1_edge(const int* __restrict__ src, const int* __restrict__ dst)
{
    int i = blockIdx.x * blockDim.x + threadIdx.x;
    if (i >= EE) return;
    int s = src[i], d = dst[i];
    float4 f = g_f4[s];
    float v = f.w + g_er1[d];
    v = v > 0.f ? v : 0.2f * v;
    float p = __expf(v);
    asm volatile("red.global.add.v4.f32 [%0], {%1, %2, %3, %4};"
                 :: "l"(&g_agg4[d]), "f"(p * f.x), "f"(p * f.y), "f"(p * f.z), "f"(p)
                 : "memory");
}

// ---------------- K45: per-node normalize, 3->64 expand, relu, el2/er2 ----------------
__global__ void __launch_bounds__(256) k45_nodes(
    const float* __restrict__ W1, const float* __restrict__ b1,
    const float* __restrict__ W2, const float* __restrict__ al2,
    const float* __restrict__ ar2)
{
    __shared__ float sW1[3 * 64];
    __shared__ float sb1[64], swa2[64], swr2[64];
    int t = threadIdx.x;
    for (int idx = t; idx < 3 * 64; idx += 256)
        sW1[idx] = W1[(idx >> 6) * 128 + (idx & 63)];
    if (t < 64) {
        sb1[t] = b1[t];
        float a = 0.f;
        for (int j = 0; j < EMBD; j++) a += W2[t * 60 + j] * al2[j];
        swa2[t] = a;
    } else if (t < 128) {
        int k = t - 64;
        float a = 0.f;
        for (int j = 0; j < EMBD; j++) a += W2[k * 60 + j] * ar2[j];
        swr2[k] = a;
    }
    __syncthreads();

    int n = blockIdx.x * 256 + t;
    if (n >= NN) return;

    float4 a = g_agg4[n];
    float inv = (a.w > 0.f) ? (1.f / a.w) : 0.f;
    float a0 = a.x * inv, a1 = a.y * inv, a2 = a.z * inv;

    float el = 0.f, er = 0.f;
#pragma unroll
    for (int kc = 0; kc < 64; kc += 8) {
#pragma unroll
        for (int u = 0; u < 8; u++) {
            float v = a0 * sW1[kc + u] + a1 * sW1[64 + kc + u] + a2 * sW1[128 + kc + u]
                    + sb1[kc + u];
            v = v > 0.f ? v : 0.f;
            el += v * swa2[kc + u];
            er += v * swr2[kc + u];
        }
    }
    g_el2[n] = el;
    g_er2[n] = er;
}

// ---------------- E2A: p2 store (coalesced) + den2 RED ----------------
__global__ void e2a_edge(const int* __restrict__ src, const int* __restrict__ dst)
{
    int i = blockIdx.x * blockDim.x + threadIdx.x;
    if (i >= EE) return;
    int s = src[i], d = dst[i];
    float v = g_el2[s] + g_er2[d];
    v = v > 0.f ? v : 0.2f * v;
    float p = __expf(v);
    g_p2[i] = p;
    atomicAdd(&g_den2[d], p);
}

// ---------------- E2C: per-src alpha sum (coalesced p2 read) ----------------
__global__ void e2c_edge(const int* __restrict__ src, const int* __restrict__ dst)
{
    int i = blockIdx.x * blockDim.x + threadIdx.x;
    if (i >= EE) return;
    float alpha = g_p2[i] / g_den2[dst[i]];
    atomicAdd(&g_w[src[i]], alpha);
}

// ---------------- K78: S64 reduce (recompute r1 from agg4) + last-block finale ----------------
__global__ void __launch_bounds__(256) k78_final(
    const float* __restrict__ W1, const float* __restrict__ b1,
    const float* __restrict__ W2, const float* __restrict__ b2,
    const float* __restrict__ vocab, const float* __restrict__ W_lin4,
    float* __restrict__ out)
{
    __shared__ float sW1[3 * 64];
    __shared__ float sb1[64];
    __shared__ float sacc[64];
    int t = threadIdx.x;
    for (int idx = t; idx < 3 * 64; idx += 256)
        sW1[idx] = W1[(idx >> 6) * 128 + (idx & 63)];
    if (t < 64) { sb1[t] = b1[t]; sacc[t] = 0.f; }
    __syncthreads();

    int lane = t & 31, wrp = t >> 5;
    int gw = blockIdx.x * 8 + wrp;
    int nw = gridDim.x * 8;
    int j = 2 * lane;
    float w10 = sW1[j],      w11 = sW1[64 + j],      w12 = sW1[128 + j],      bb0 = sb1[j];
    float w20 = sW1[j + 1],  w21 = sW1[64 + j + 1],  w22 = sW1[128 + j + 1],  bb1 = sb1[j + 1];

    float ax = 0.f, ay = 0.f;
    for (int n = gw; n < NN; n += nw) {
        float4 a = g_agg4[n];
        float wn = g_w[n];
        float inv = (a.w > 0.f) ? (1.f / a.w) : 0.f;
        float a0 = a.x * inv, a1 = a.y * inv, a2 = a.z * inv;
        float r0 = a0 * w10 + a1 * w11 + a2 * w12 + bb0;
        float r1 = a0 * w20 + a1 * w21 + a2 * w22 + bb1;
        r0 = r0 > 0.f ? r0 : 0.f;
        r1 = r1 > 0.f ? r1 : 0.f;
        ax = fmaf(wn, r0, ax);
        ay = fmaf(wn, r1, ay);
    }
    atomicAdd(&sacc[j], ax);
    atomicAdd(&sacc[j + 1], ay);
    __syncthreads();
    if (t < 64) atomicAdd(&g_s64[t], sacc[t]);

    // last-block detection
    __threadfence();
    __syncthreads();
    __shared__ int isLast;
    if (t == 0) isLast = (atomicAdd(&g_ctr, 1) == (int)gridDim.x - 1);
    __syncthreads();
    if (!isLast) return;

    __shared__ float h[70];
    __shared__ float l[2];
    if (t < 30) {
        float acc = 0.f;
        for (int k = 0; k < 64; k++) acc += __ldcg(&g_s64[k]) * W2[k * 60 + t];
        h[t] = acc * (1.f / (float)NN) + b2[t];
    }
    else if (t < 60) h[t] = g_himg[t - 30];
    else if (t < 70) h[t] = vocab[t - 60];
    __syncthreads();
    if (t < 2) {
        float acc = 0.f;
        for (int k = 0; k < 70; k++) acc += W_lin4[t * 70 + k] * h[k];
        l[t] = acc;
    }
    __syncthreads();
    if (t < 2) {
        float m = fmaxf(l[0], l[1]);
        float lse = m + logf(expf(l[0] - m) + expf(l[1] - m));
        out[t] = l[t] - lse;
    }
}

// ---------------- launch ----------------
extern "C" void kernel_launch(void* const* d_in, const int* in_sizes, int n_in,
                              void* d_out, int out_size)
{
    const float* x       = (const float*)d_in[0];
    const float* feat    = (const float*)d_in[1];
    const float* vocab   = (const float*)d_in[2];
    const int*   src     = (const int*)d_in[3];
    const int*   dst     = (const int*)d_in[4];
    const float* W_lin1  = (const float*)d_in[5];
    const float* w_conv2 = (const float*)d_in[6];
    const float* w_conv3 = (const float*)d_in[7];
    const float* W_lin4  = (const float*)d_in[8];
    const float* W1      = (const float*)d_in[9];
    const float* al1     = (const float*)d_in[10];
    const float* ar1     = (const float*)d_in[11];
    const float* b1      = (const float*)d_in[12];
    const float* W2      = (const float*)d_in[13];
    const float* al2     = (const float*)d_in[14];
    const float* ar2     = (const float*)d_in[15];
    const float* b2      = (const float*)d_in[16];
    float* out = (float*)d_out;

    k1_init<<<NODE_BLOCKS + 1, 256>>>(feat, al1, ar1, W1, x, W_lin1, w_conv2, w_conv3);
    e1_edge<<<(EE + 255) / 256, 256>>>(src, dst);
    k45_nodes<<<(NN + 255) / 256, 256>>>(W1, b1, W2, al2, ar2);
    e2a_edge<<<(EE + 255) / 256, 256>>>(src, dst);
    e2c_edge<<<(EE + 255) / 256, 256>>>(src, dst);
    k78_final<<<160, 256>>>(W1, b1, W2, b2, vocab, W_lin4, out);
}